// round 2
// baseline (speedup 1.0000x reference)
#include <cuda_runtime.h>
#include <float.h>
#include <math.h>

#define NN   2048
#define BBATCH 4
#define SS   1024
#define SFZ  384
#define IFZ  256
#define HH   8
#define AA   64
#define HA   512
#define MAXT 36

// ---------------- static device scratch (no allocations) -------------------
__device__ float g_q[NN * HA];
__device__ float g_gate[NN * HA];
__device__ float g_k[BBATCH * SS * HA];
__device__ float g_v[BBATCH * SS * HA];
__device__ float g_feat[NN * HA];
__device__ float g_y[NN * IFZ];
__device__ unsigned char g_mask[BBATCH * SS];
__device__ int g_tb[MAXT], g_ts[MAXT], g_tc[MAXT], g_nt;

// ---------------- 4x4 outer-product FMA ------------------------------------
__device__ __forceinline__ void fma16(float (&acc)[4][4], float4 a, float4 b) {
    acc[0][0] += a.x * b.x; acc[0][1] += a.x * b.y; acc[0][2] += a.x * b.z; acc[0][3] += a.x * b.w;
    acc[1][0] += a.y * b.x; acc[1][1] += a.y * b.y; acc[1][2] += a.y * b.z; acc[1][3] += a.y * b.w;
    acc[2][0] += a.z * b.x; acc[2][1] += a.z * b.y; acc[2][2] += a.z * b.z; acc[2][3] += a.z * b.w;
    acc[3][0] += a.w * b.x; acc[3][1] += a.w * b.y; acc[3][2] += a.w * b.z; acc[3][3] += a.w * b.w;
}

// ---------------- prep: dtype canonicalization + node tiles ----------------
__global__ void prep_k(const void* mask_in, const void* batch_in) {
    __shared__ int flg[2];      // [0]=batch is int32, [1]=mask is bool
    __shared__ int cnt[BBATCH];
    int tid = threadIdx.x;
    if (tid < 2) flg[tid] = 0;
    if (tid < BBATCH) cnt[tid] = 0;
    __syncthreads();

    // batch dtype probe: if int64, odd 32-bit words (high halves) are all 0.
    const unsigned int* bw = (const unsigned int*)batch_in;
    unsigned int o = 0;
    for (int i = tid * 2 + 1; i < NN; i += blockDim.x * 2) o |= bw[i];
    if (o) atomicOr(&flg[0], 1);

    // mask dtype probe: bool array has nonzero bytes at (i&3)!=0 positions.
    const unsigned char* mb = (const unsigned char*)mask_in;
    int f = 0;
    for (int i = tid; i < BBATCH * SS; i += blockDim.x)
        if ((i & 3) && mb[i]) f = 1;
    if (f) atomicOr(&flg[1], 1);
    __syncthreads();

    int is32 = flg[0], isb = flg[1];
    int lc[BBATCH] = {0, 0, 0, 0};
    for (int i = tid; i < NN; i += blockDim.x) {
        int v = is32 ? ((const int*)batch_in)[i]
                     : (int)((const long long*)batch_in)[i];
        lc[v & 3]++;
    }
    #pragma unroll
    for (int b = 0; b < BBATCH; b++) if (lc[b]) atomicAdd(&cnt[b], lc[b]);

    for (int i = tid; i < BBATCH * SS; i += blockDim.x)
        g_mask[i] = isb ? (mb[i] ? 1 : 0) : (((const int*)mask_in)[i] ? 1 : 0);
    __syncthreads();

    if (tid == 0) {
        int st = 0, t = 0;
        for (int b = 0; b < BBATCH; b++) {
            int e = st + cnt[b];
            for (int s = st; s < e; s += 64) {
                g_tb[t] = b; g_ts[t] = s; g_tc[t] = min(64, e - s); t++;
            }
            st = e;
        }
        g_nt = t;
    }
}

// ---------------- q = x@Wq ; gate = sigmoid(x@Wg + bg) ---------------------
__global__ void __launch_bounds__(256) proj_qg_k(const float* __restrict__ x,
                                                 const float* __restrict__ Wq,
                                                 const float* __restrict__ Wg,
                                                 const float* __restrict__ bg) {
    __shared__ float As[16][68];
    __shared__ float Bs[16][64];
    int tid = threadIdx.x, tx = tid & 15, ty = tid >> 4;
    int m0 = blockIdx.x * 64, n0 = blockIdx.y * 64;
    bool isg = (n0 >= HA);
    const float* W = isg ? Wg : Wq;
    int nc0 = isg ? (n0 - HA) : n0;
    float acc[4][4] = {};
    int lm = tid >> 2, lk = (tid & 3) * 4;
    int bk = tid >> 4, bn = (tid & 15) * 4;
    for (int k0 = 0; k0 < IFZ; k0 += 16) {
        float4 a = *(const float4*)(x + (size_t)(m0 + lm) * IFZ + k0 + lk);
        As[lk + 0][lm] = a.x; As[lk + 1][lm] = a.y; As[lk + 2][lm] = a.z; As[lk + 3][lm] = a.w;
        *(float4*)&Bs[bk][bn] = *(const float4*)(W + (size_t)(k0 + bk) * HA + nc0 + bn);
        __syncthreads();
        #pragma unroll
        for (int kk = 0; kk < 16; kk++) {
            float4 a4 = *(float4*)&As[kk][ty * 4];
            float4 b4 = *(float4*)&Bs[kk][tx * 4];
            fma16(acc, a4, b4);
        }
        __syncthreads();
    }
    if (isg) {
        float4 bgv = *(const float4*)(bg + nc0 + tx * 4);
        #pragma unroll
        for (int i = 0; i < 4; i++) {
            int row = m0 + ty * 4 + i;
            float4 o;
            o.x = 1.0f / (1.0f + __expf(-(acc[i][0] + bgv.x)));
            o.y = 1.0f / (1.0f + __expf(-(acc[i][1] + bgv.y)));
            o.z = 1.0f / (1.0f + __expf(-(acc[i][2] + bgv.z)));
            o.w = 1.0f / (1.0f + __expf(-(acc[i][3] + bgv.w)));
            *(float4*)&g_gate[(size_t)row * HA + nc0 + tx * 4] = o;
        }
    } else {
        #pragma unroll
        for (int i = 0; i < 4; i++) {
            int row = m0 + ty * 4 + i;
            *(float4*)&g_q[(size_t)row * HA + nc0 + tx * 4] =
                make_float4(acc[i][0], acc[i][1], acc[i][2], acc[i][3]);
        }
    }
}

// ---------------- k = emb@Wk ; v = emb@Wv ----------------------------------
__global__ void __launch_bounds__(256) proj_kv_k(const float* __restrict__ emb,
                                                 const float* __restrict__ Wk,
                                                 const float* __restrict__ Wv) {
    __shared__ float As[16][68];
    __shared__ float Bs[16][64];
    int tid = threadIdx.x, tx = tid & 15, ty = tid >> 4;
    int m0 = blockIdx.x * 64, n0 = blockIdx.y * 64;
    bool isv = (n0 >= HA);
    const float* W = isv ? Wv : Wk;
    float* Cout = isv ? g_v : g_k;
    int nc0 = isv ? (n0 - HA) : n0;
    float acc[4][4] = {};
    int lm = tid >> 2, lk = (tid & 3) * 4;
    int bk = tid >> 4, bn = (tid & 15) * 4;
    for (int k0 = 0; k0 < SFZ; k0 += 16) {
        float4 a = *(const float4*)(emb + (size_t)(m0 + lm) * SFZ + k0 + lk);
        As[lk + 0][lm] = a.x; As[lk + 1][lm] = a.y; As[lk + 2][lm] = a.z; As[lk + 3][lm] = a.w;
        *(float4*)&Bs[bk][bn] = *(const float4*)(W + (size_t)(k0 + bk) * HA + nc0 + bn);
        __syncthreads();
        #pragma unroll
        for (int kk = 0; kk < 16; kk++) {
            float4 a4 = *(float4*)&As[kk][ty * 4];
            float4 b4 = *(float4*)&Bs[kk][tx * 4];
            fma16(acc, a4, b4);
        }
        __syncthreads();
    }
    #pragma unroll
    for (int i = 0; i < 4; i++) {
        int row = m0 + ty * 4 + i;
        *(float4*)&Cout[(size_t)row * HA + nc0 + tx * 4] =
            make_float4(acc[i][0], acc[i][1], acc[i][2], acc[i][3]);
    }
}

// ---------------- attention: flash masked softmax + gated feature ----------
// grid (MAXT, HH), 256 threads. One 64-node tile x one head per block.
__global__ void __launch_bounds__(256) attn_k(float* __restrict__ logits) {
    int t = blockIdx.x;
    if (t >= g_nt) return;
    int h = blockIdx.y;
    int b = g_tb[t], n0 = g_ts[t], cnt = g_tc[t];
    __shared__ float Qs[64 * 64];   // Q^T  [a][i]
    __shared__ float KP[64 * 64];   // K^T [a][j], then P^T [j][i]
    __shared__ float Vs[64 * 64];   // V   [j][a]
    int tid = threadIdx.x, tx = tid & 15, ty = tid >> 4;
    int lr = tid >> 2, la = (tid & 3) * 16;

    // load Q tile transposed (zero-pad invalid rows); loaded ONCE per block
    #pragma unroll
    for (int q = 0; q < 4; q++) {
        float4 v = make_float4(0.f, 0.f, 0.f, 0.f);
        if (lr < cnt)
            v = *(const float4*)&g_q[(size_t)(n0 + lr) * HA + h * AA + la + q * 4];
        int a = la + q * 4;
        Qs[(a + 0) * 64 + lr] = v.x; Qs[(a + 1) * 64 + lr] = v.y;
        Qs[(a + 2) * 64 + lr] = v.z; Qs[(a + 3) * 64 + lr] = v.w;
    }

    float m[4], l[4], feat[4][4];
    #pragma unroll
    for (int r = 0; r < 4; r++) {
        m[r] = -FLT_MAX; l[r] = 0.f;
        #pragma unroll
        for (int c = 0; c < 4; c++) feat[r][c] = 0.f;
    }

    for (int s0 = 0; s0 < SS; s0 += 64) {
        __syncthreads();   // prior P consumption done before overwriting KP
        #pragma unroll
        for (int q = 0; q < 4; q++) {
            int a = la + q * 4;
            size_t rb = (size_t)((b << 10) + s0 + lr) * HA + h * AA + a;
            float4 kv = *(const float4*)&g_k[rb];
            KP[(a + 0) * 64 + lr] = kv.x; KP[(a + 1) * 64 + lr] = kv.y;
            KP[(a + 2) * 64 + lr] = kv.z; KP[(a + 3) * 64 + lr] = kv.w;
            *(float4*)&Vs[lr * 64 + a] = *(const float4*)&g_v[rb];
        }
        __syncthreads();

        // scores chunk: Sc = Q @ K^T / 8
        float sc[4][4] = {};
        #pragma unroll 8
        for (int a = 0; a < 64; a++) {
            float4 q4 = *(float4*)&Qs[a * 64 + ty * 4];
            float4 k4 = *(float4*)&KP[a * 64 + tx * 4];
            fma16(sc, q4, k4);
        }
        #pragma unroll
        for (int r = 0; r < 4; r++)
            #pragma unroll
            for (int c = 0; c < 4; c++) sc[r][c] *= 0.125f;

        // raw-score logits from heads 0,1 (exactly 2 adds/element, zeroed buffer)
        if (h < 2) {
            #pragma unroll
            for (int r = 0; r < 4; r++) {
                int i = ty * 4 + r;
                if (i < cnt) {
                    #pragma unroll
                    for (int c = 0; c < 4; c++)
                        atomicAdd(&logits[(size_t)(n0 + i) * SS + s0 + tx * 4 + c],
                                  sc[r][c]);
                }
            }
        }

        // mask for this thread's 4 columns
        unsigned int mw = *(const unsigned int*)&g_mask[b * SS + s0 + tx * 4];
        float mk[4] = {(float)(mw & 255u), (float)((mw >> 8) & 255u),
                       (float)((mw >> 16) & 255u), (float)((mw >> 24) & 255u)};

        // online softmax update per row (16-lane shuffle groups == rows)
        #pragma unroll
        for (int r = 0; r < 4; r++) {
            float v = -FLT_MAX;
            #pragma unroll
            for (int c = 0; c < 4; c++)
                v = fmaxf(v, mk[c] > 0.f ? sc[r][c] : -FLT_MAX);
            #pragma unroll
            for (int d = 8; d; d >>= 1)
                v = fmaxf(v, __shfl_xor_sync(0xffffffffu, v, d, 16));
            float mn = fmaxf(m[r], v);
            float alpha = __expf(m[r] - mn);
            float sum = 0.f;
            #pragma unroll
            for (int c = 0; c < 4; c++) {
                float p = mk[c] > 0.f ? __expf(sc[r][c] - mn) : 0.f;
                sc[r][c] = p; sum += p;
            }
            #pragma unroll
            for (int d = 8; d; d >>= 1)
                sum += __shfl_xor_sync(0xffffffffu, sum, d, 16);
            l[r] = l[r] * alpha + sum;
            m[r] = mn;
            #pragma unroll
            for (int c = 0; c < 4; c++) feat[r][c] *= alpha;
        }

        // stage P^T into KP (reuse), then feat += P @ V
        __syncthreads();
        #pragma unroll
        for (int r = 0; r < 4; r++)
            #pragma unroll
            for (int c = 0; c < 4; c++)
                KP[(tx * 4 + c) * 64 + ty * 4 + r] = sc[r][c];
        __syncthreads();
        #pragma unroll 8
        for (int j = 0; j < 64; j++) {
            float4 p4 = *(float4*)&KP[j * 64 + ty * 4];
            float4 v4 = *(float4*)&Vs[j * 64 + tx * 4];
            fma16(feat, p4, v4);
        }
    }

    // epilogue: normalize (sum + 1e-9), apply gate, store
    #pragma unroll
    for (int r = 0; r < 4; r++) {
        int i = ty * 4 + r;
        if (i >= cnt) continue;
        float inv = 1.f / (l[r] + 1e-9f);
        size_t base = (size_t)(n0 + i) * HA + h * AA + tx * 4;
        float4 g = *(const float4*)&g_gate[base];
        float4 o;
        o.x = feat[r][0] * inv * g.x; o.y = feat[r][1] * inv * g.y;
        o.z = feat[r][2] * inv * g.z; o.w = feat[r][3] * inv * g.w;
        *(float4*)&g_feat[base] = o;
    }
}

// ---------------- y = sqrt(2)*x + gatedfeat @ Wback + bback ----------------
__global__ void __launch_bounds__(256) back_k(const float* __restrict__ x,
                                              const float* __restrict__ Wback,
                                              const float* __restrict__ bback) {
    __shared__ float As[16][68];
    __shared__ float Bs[16][64];
    int tid = threadIdx.x, tx = tid & 15, ty = tid >> 4;
    int m0 = blockIdx.x * 64, n0 = blockIdx.y * 64;
    float acc[4][4] = {};
    int lm = tid >> 2, lk = (tid & 3) * 4;
    int bk = tid >> 4, bn = (tid & 15) * 4;
    for (int k0 = 0; k0 < HA; k0 += 16) {
        float4 a = *(const float4*)&g_feat[(size_t)(m0 + lm) * HA + k0 + lk];
        As[lk + 0][lm] = a.x; As[lk + 1][lm] = a.y; As[lk + 2][lm] = a.z; As[lk + 3][lm] = a.w;
        *(float4*)&Bs[bk][bn] = *(const float4*)&Wback[(size_t)(k0 + bk) * IFZ + n0 + bn];
        __syncthreads();
        #pragma unroll
        for (int kk = 0; kk < 16; kk++) {
            float4 a4 = *(float4*)&As[kk][ty * 4];
            float4 b4 = *(float4*)&Bs[kk][tx * 4];
            fma16(acc, a4, b4);
        }
        __syncthreads();
    }
    const float rt2 = 1.41421356237309515f;
    float4 bb = *(const float4*)&bback[n0 + tx * 4];
    #pragma unroll
    for (int i = 0; i < 4; i++) {
        int row = m0 + ty * 4 + i;
        float4 xv = *(const float4*)&x[(size_t)row * IFZ + n0 + tx * 4];
        float4 o;
        o.x = rt2 * xv.x + acc[i][0] + bb.x;
        o.y = rt2 * xv.y + acc[i][1] + bb.y;
        o.z = rt2 * xv.z + acc[i][2] + bb.z;
        o.w = rt2 * xv.w + acc[i][3] + bb.w;
        *(float4*)&g_y[(size_t)row * IFZ + n0 + tx * 4] = o;
    }
}

// ---------------- LayerNorm: warp per row ----------------------------------
__global__ void __launch_bounds__(256) ln_k(const float* __restrict__ gamma,
                                            const float* __restrict__ beta,
                                            float* __restrict__ out) {
    int warp = threadIdx.x >> 5, lane = threadIdx.x & 31;
    int row = blockIdx.x * 8 + warp;
    float4 v0 = *(const float4*)&g_y[(size_t)row * IFZ + lane * 4];
    float4 v1 = *(const float4*)&g_y[(size_t)row * IFZ + 128 + lane * 4];
    float s = v0.x + v0.y + v0.z + v0.w + v1.x + v1.y + v1.z + v1.w;
    #pragma unroll
    for (int d = 16; d; d >>= 1) s += __shfl_xor_sync(0xffffffffu, s, d);
    float mu = s * (1.f / 256.f);
    float q = 0.f;
    q += (v0.x - mu) * (v0.x - mu); q += (v0.y - mu) * (v0.y - mu);
    q += (v0.z - mu) * (v0.z - mu); q += (v0.w - mu) * (v0.w - mu);
    q += (v1.x - mu) * (v1.x - mu); q += (v1.y - mu) * (v1.y - mu);
    q += (v1.z - mu) * (v1.z - mu); q += (v1.w - mu) * (v1.w - mu);
    #pragma unroll
    for (int d = 16; d; d >>= 1) q += __shfl_xor_sync(0xffffffffu, q, d);
    float inv = rsqrtf(q * (1.f / 256.f) + 1e-5f);
    float4 g0 = *(const float4*)&gamma[lane * 4];
    float4 b0 = *(const float4*)&beta[lane * 4];
    float4 g1 = *(const float4*)&gamma[128 + lane * 4];
    float4 b1 = *(const float4*)&beta[128 + lane * 4];
    float4 o0, o1;
    o0.x = (v0.x - mu) * inv * g0.x + b0.x;
    o0.y = (v0.y - mu) * inv * g0.y + b0.y;
    o0.z = (v0.z - mu) * inv * g0.z + b0.z;
    o0.w = (v0.w - mu) * inv * g0.w + b0.w;
    o1.x = (v1.x - mu) * inv * g1.x + b1.x;
    o1.y = (v1.y - mu) * inv * g1.y + b1.y;
    o1.z = (v1.z - mu) * inv * g1.z + b1.z;
    o1.w = (v1.w - mu) * inv * g1.w + b1.w;
    *(float4*)&out[(size_t)row * IFZ + lane * 4] = o0;
    *(float4*)&out[(size_t)row * IFZ + 128 + lane * 4] = o1;
}

// ---------------- launch ---------------------------------------------------
extern "C" void kernel_launch(void* const* d_in, const int* in_sizes, int n_in,
                              void* d_out, int out_size) {
    const float* x     = (const float*)d_in[0];
    const float* emb   = (const float*)d_in[1];
    const void*  mask  = d_in[2];
    const void*  batch = d_in[3];
    const float* Wq    = (const float*)d_in[4];
    const float* Wk    = (const float*)d_in[5];
    const float* Wv    = (const float*)d_in[6];
    const float* Wg    = (const float*)d_in[7];
    const float* bg    = (const float*)d_in[8];
    const float* Wback = (const float*)d_in[9];
    const float* bback = (const float*)d_in[10];
    const float* gamma = (const float*)d_in[11];
    const float* beta  = (const float*)d_in[12];
    float* out    = (float*)d_out;
    float* logits = out + (size_t)NN * IFZ;

    cudaMemsetAsync(logits, 0, (size_t)NN * SS * sizeof(float), 0);
    prep_k<<<1, 256>>>(mask, batch);
    proj_qg_k<<<dim3(32, 16), 256>>>(x, Wq, Wg, bg);
    proj_kv_k<<<dim3(64, 16), 256>>>(emb, Wk, Wv);
    attn_k<<<dim3(MAXT, HH), 256>>>(logits);
    back_k<<<dim3(32, 4), 256>>>(x, Wback, bback);
    ln_k<<<256, 256>>>(gamma, beta, out);
}